// round 6
// baseline (speedup 1.0000x reference)
#include <cuda_runtime.h>
#include <cstdint>

#define BATCH 32
#define TDIM  2048
#define CDIM  384
#define HDIM  64
#define BT    (BATCH * TDIM)
#define NQT   32                       // 64-row query tiles

// Projected activations (pre-rounded to tf32 by proj epilogue).
__device__ float g_q[BT * HDIM];
__device__ float g_k[BT * HDIM];
__device__ float g_v[BT * HDIM];

__device__ __forceinline__ float tf32r(float x) {
    asm("cvt.rna.tf32.f32 %0, %1;" : "=f"(x) : "f"(x));
    return x;
}
__device__ __forceinline__ uint32_t fu(float x) { return __float_as_uint(x); }

__device__ __forceinline__ uint32_t smem_u32(const void* p) {
    uint32_t a;
    asm("{ .reg .u64 t; cvta.to.shared.u64 t, %1; cvt.u32.u64 %0, t; }"
        : "=r"(a) : "l"(p));
    return a;
}
__device__ __forceinline__ void cpa16(uint32_t dst, const void* src) {
    asm volatile("cp.async.cg.shared.global [%0], [%1], 16;"
                 :: "r"(dst), "l"(src));
}
#define CPCOMMIT() asm volatile("cp.async.commit_group;" ::: "memory")
#define CPWAIT(n)  asm volatile("cp.async.wait_group %0;" :: "n"(n) : "memory")

// m16n8k8 tf32 MMA, D = A*B + D.
// A frag: a0(r=l>>2,k=l&3) a1(r+8,k) a2(r,k+4) a3(r+8,k+4)
// B frag: b0(k=l&3,n=l>>2) b1(k+4,n)
// C frag: c0(r=l>>2,n=2(l&3)) c1(n+1) c2(r+8,n) c3(r+8,n+1)
__device__ __forceinline__ void mma8(float4& c, const uint32_t a[4],
                                     uint32_t b0, uint32_t b1) {
    asm volatile(
        "mma.sync.aligned.m16n8k8.row.col.f32.tf32.tf32.f32 "
        "{%0,%1,%2,%3}, {%4,%5,%6,%7}, {%8,%9}, {%0,%1,%2,%3};"
        : "+f"(c.x), "+f"(c.y), "+f"(c.z), "+f"(c.w)
        : "r"(a[0]), "r"(a[1]), "r"(a[2]), "r"(a[3]), "r"(b0), "r"(b1));
}

// ---------------------------------------------------------------------------
// Projection: [K|Q|V] = x @ [Wk|Wq|Wv]. Block = 256 thr (8 warps), 128 rows.
// Same as R4, but epilogue rounds outputs to tf32 (so attn can stage raw).
// ---------------------------------------------------------------------------
__global__ __launch_bounds__(256, 1) void proj_kernel(
    const float* __restrict__ x,
    const float* __restrict__ Wk,
    const float* __restrict__ Wq,
    const float* __restrict__ Wv)
{
    __shared__ float Xs[128 * 36];
    __shared__ float Ws[3 * 32 * 72];

    const int t    = threadIdx.x;
    const int warp = t >> 5;
    const int lane = t & 31;
    const int q    = lane & 3;
    const int r4   = lane >> 2;
    const int row0 = blockIdx.x * 128;
    const float* Wm[3] = {Wk, Wq, Wv};

    float4 c[24];
    #pragma unroll
    for (int i = 0; i < 24; i++) c[i] = make_float4(0.f, 0.f, 0.f, 0.f);

    float4 xr[4], wr[6];
    #pragma unroll
    for (int i = 0; i < 4; i++) {
        int f = t + i * 256, r = f >> 3, c4 = f & 7;
        xr[i] = *(const float4*)&x[(row0 + r) * CDIM + c4 * 4];
    }
    #pragma unroll
    for (int j = 0; j < 6; j++) {
        int g = t + (j & 1) * 256, k = g >> 4, h4 = g & 15;
        wr[j] = *(const float4*)&Wm[j >> 1][k * HDIM + h4 * 4];
    }

    for (int cc = 0; cc < 12; cc++) {
        __syncthreads();
        #pragma unroll
        for (int i = 0; i < 4; i++) {
            int f = t + i * 256, r = f >> 3, c4 = f & 7;
            *(float4*)&Xs[r * 36 + c4 * 4] = make_float4(
                tf32r(xr[i].x), tf32r(xr[i].y), tf32r(xr[i].z), tf32r(xr[i].w));
        }
        #pragma unroll
        for (int j = 0; j < 6; j++) {
            int g = t + (j & 1) * 256, k = g >> 4, h4 = g & 15;
            *(float4*)&Ws[(j >> 1) * 2304 + k * 72 + h4 * 4] = make_float4(
                tf32r(wr[j].x), tf32r(wr[j].y), tf32r(wr[j].z), tf32r(wr[j].w));
        }
        __syncthreads();

        if (cc + 1 < 12) {
            const int c0 = (cc + 1) * 32;
            #pragma unroll
            for (int i = 0; i < 4; i++) {
                int f = t + i * 256, r = f >> 3, c4 = f & 7;
                xr[i] = *(const float4*)&x[(row0 + r) * CDIM + c0 + c4 * 4];
            }
            #pragma unroll
            for (int j = 0; j < 6; j++) {
                int g = t + (j & 1) * 256, k = g >> 4, h4 = g & 15;
                wr[j] = *(const float4*)&Wm[j >> 1][(c0 + k) * HDIM + h4 * 4];
            }
        }

        uint32_t a[4][4];
        #pragma unroll
        for (int kc = 0; kc < 4; kc++) {
            const int rb = (warp * 16 + r4) * 36 + 8 * kc + q;
            a[kc][0] = fu(Xs[rb]);
            a[kc][1] = fu(Xs[rb + 8 * 36]);
            a[kc][2] = fu(Xs[rb + 4]);
            a[kc][3] = fu(Xs[rb + 8 * 36 + 4]);
        }
        #pragma unroll
        for (int mat = 0; mat < 3; mat++)
            #pragma unroll
            for (int nc = 0; nc < 8; nc++)
                #pragma unroll
                for (int kc = 0; kc < 4; kc++) {
                    uint32_t b0 = fu(Ws[mat * 2304 + (8 * kc + q)     * 72 + 8 * nc + r4]);
                    uint32_t b1 = fu(Ws[mat * 2304 + (8 * kc + q + 4) * 72 + 8 * nc + r4]);
                    mma8(c[mat * 8 + nc], a[kc], b0, b1);
                }
    }

    const int row = row0 + warp * 16 + r4;
    float* outp[3] = {g_k, g_q, g_v};
    #pragma unroll
    for (int mat = 0; mat < 3; mat++)
        #pragma unroll
        for (int nc = 0; nc < 8; nc++) {
            const int col = 8 * nc + 2 * q;
            float4 v = c[mat * 8 + nc];
            *(float2*)&outp[mat][row * HDIM + col] =
                make_float2(tf32r(v.x), tf32r(v.y));
            *(float2*)&outp[mat][(row + 8) * HDIM + col] =
                make_float2(tf32r(v.z), tf32r(v.w));
        }
}

// ---------------------------------------------------------------------------
// Flash attention, warp-MMA tf32. Block = 128 thr (4 warps), 64 q-rows.
// grid (32, 32), heavy tiles first. K/V staged raw via cp.async into
// double-buffered dynamic smem (values pre-rounded to tf32 in gmem).
// Smem words: buf b at b*8960: K 64x68, then V 64x72.
// ---------------------------------------------------------------------------
#define KPITCH 68
#define VPITCH 72
#define KSZ    (64 * KPITCH)
#define BUFW   (KSZ + 64 * VPITCH)     // 8960 words
#define ASMEM  (2 * BUFW * 4)          // 71680 bytes

__global__ __launch_bounds__(128, 3) void attn_kernel(float* __restrict__ out)
{
    extern __shared__ float sm[];
    const uint32_t sb = smem_u32(sm);

    const int t    = threadIdx.x;
    const int b    = blockIdx.y;
    const int warp = t >> 5;
    const int lane = t & 31;
    const int q    = lane & 3;
    const int r4   = lane >> 2;
    const int srcA = (lane & ~3) | (q >> 1);
    const int srcB = srcA + 2;

    const int qt     = (NQT - 1) - (int)blockIdx.x;   // heavy first
    const int nkt    = qt + 1;
    const int row_lo = qt * 64 + warp * 16 + r4;

    const float* kb0 = g_k + (b * TDIM) * HDIM;
    const float* vb0 = g_v + (b * TDIM) * HDIM;

    // stage tile kt into buffer buf (raw copy; data already tf32-rounded)
    auto stage = [&](int kt, int buf) {
        const float* kb = kb0 + kt * 64 * HDIM;
        const float* vb = vb0 + kt * 64 * HDIM;
        const uint32_t base = sb + (uint32_t)(buf * BUFW) * 4u;
        #pragma unroll
        for (int i = 0; i < 8; i++) {
            int f = t + i * 128, key = f >> 4, c4 = (f & 15) << 2;
            cpa16(base + (uint32_t)(key * KPITCH + c4) * 4u, kb + key * HDIM + c4);
        }
        #pragma unroll
        for (int i = 0; i < 8; i++) {
            int f = t + i * 128, key = f >> 4, c4 = (f & 15) << 2;
            cpa16(base + (uint32_t)(KSZ + key * VPITCH + c4) * 4u, vb + key * HDIM + c4);
        }
        CPCOMMIT();
    };

    stage(0, 0);

    // Q fragments (pre-scaled; values already tf32 so *0.125 stays exact)
    uint32_t qa[8][4];
    {
        const float* qp = g_q + (b * TDIM + row_lo) * HDIM;
        #pragma unroll
        for (int kc = 0; kc < 8; kc++) {
            qa[kc][0] = fu(tf32r(qp[8 * kc + q] * 0.125f));
            qa[kc][1] = fu(tf32r(qp[8 * HDIM + 8 * kc + q] * 0.125f));
            qa[kc][2] = fu(tf32r(qp[8 * kc + q + 4] * 0.125f));
            qa[kc][3] = fu(tf32r(qp[8 * HDIM + 8 * kc + q + 4] * 0.125f));
        }
    }

    float4 o[8];
    #pragma unroll
    for (int i = 0; i < 8; i++) o[i] = make_float4(0.f, 0.f, 0.f, 0.f);
    float m0 = -1e30f, m1 = -1e30f, l0 = 0.f, l1 = 0.f;

    for (int kt = 0; kt < nkt; kt++) {
        if (kt + 1 < nkt) { stage(kt + 1, (kt + 1) & 1); CPWAIT(1); }
        else              { CPWAIT(0); }
        __syncthreads();

        const float* Ks = sm + (kt & 1) * BUFW;
        const float* Vs = Ks + KSZ;

        // S = Q @ K^T
        float4 st[8];
        #pragma unroll
        for (int i = 0; i < 8; i++) st[i] = make_float4(0.f, 0.f, 0.f, 0.f);
        #pragma unroll
        for (int nc = 0; nc < 8; nc++) {
            const int rb = (8 * nc + r4) * KPITCH;
            #pragma unroll
            for (int kc = 0; kc < 8; kc++) {
                uint32_t b0 = fu(Ks[rb + 8 * kc + q]);
                uint32_t b1 = fu(Ks[rb + 8 * kc + q + 4]);
                mma8(st[nc], qa[kc], b0, b1);
            }
        }

        // causal mask: only the diagonal (last) tile clips
        if (kt == nkt - 1) {
            const int cb = kt * 64 + 2 * q;
            #pragma unroll
            for (int nc = 0; nc < 8; nc++) {
                const int col = cb + 8 * nc;
                if (col > row_lo)         st[nc].x = -1e30f;
                if (col + 1 > row_lo)     st[nc].y = -1e30f;
                if (col > row_lo + 8)     st[nc].z = -1e30f;
                if (col + 1 > row_lo + 8) st[nc].w = -1e30f;
            }
        }

        // online softmax (rows r4 / r4+8, spread across the quad)
        float mx0 = st[0].x, mx1 = st[0].z;
        #pragma unroll
        for (int nc = 0; nc < 8; nc++) {
            mx0 = fmaxf(mx0, fmaxf(st[nc].x, st[nc].y));
            mx1 = fmaxf(mx1, fmaxf(st[nc].z, st[nc].w));
        }
        mx0 = fmaxf(mx0, __shfl_xor_sync(0xffffffffu, mx0, 1));
        mx0 = fmaxf(mx0, __shfl_xor_sync(0xffffffffu, mx0, 2));
        mx1 = fmaxf(mx1, __shfl_xor_sync(0xffffffffu, mx1, 1));
        mx1 = fmaxf(mx1, __shfl_xor_sync(0xffffffffu, mx1, 2));
        const float mn0 = fmaxf(m0, mx0), mn1 = fmaxf(m1, mx1);
        const float corr0 = __expf(m0 - mn0), corr1 = __expf(m1 - mn1);
        m0 = mn0; m1 = mn1;

        float s0 = 0.f, s1 = 0.f;
        #pragma unroll
        for (int nc = 0; nc < 8; nc++) {
            st[nc].x = tf32r(__expf(st[nc].x - mn0));
            st[nc].y = tf32r(__expf(st[nc].y - mn0));
            st[nc].z = tf32r(__expf(st[nc].z - mn1));
            st[nc].w = tf32r(__expf(st[nc].w - mn1));
            s0 += st[nc].x + st[nc].y;
            s1 += st[nc].z + st[nc].w;
        }
        l0 = l0 * corr0 + s0;
        l1 = l1 * corr1 + s1;
        #pragma unroll
        for (int nc = 0; nc < 8; nc++) {
            o[nc].x *= corr0; o[nc].y *= corr0;
            o[nc].z *= corr1; o[nc].w *= corr1;
        }

        // O += P @ V   (P: C-frag -> A-frag via quad shuffles)
        #pragma unroll
        for (int kc = 0; kc < 8; kc++) {
            float u0 = __shfl_sync(0xffffffffu, st[kc].x, srcA);
            float u1 = __shfl_sync(0xffffffffu, st[kc].y, srcA);
            float a0f = (q & 1) ? u1 : u0;
            u0 = __shfl_sync(0xffffffffu, st[kc].z, srcA);
            u1 = __shfl_sync(0xffffffffu, st[kc].w, srcA);
            float a1f = (q & 1) ? u1 : u0;
            u0 = __shfl_sync(0xffffffffu, st[kc].x, srcB);
            u1 = __shfl_sync(0xffffffffu, st[kc].y, srcB);
            float a2f = (q & 1) ? u1 : u0;
            u0 = __shfl_sync(0xffffffffu, st[kc].z, srcB);
            u1 = __shfl_sync(0xffffffffu, st[kc].w, srcB);
            float a3f = (q & 1) ? u1 : u0;
            uint32_t a[4] = {fu(a0f), fu(a1f), fu(a2f), fu(a3f)};

            const int vb0o = (8 * kc + q) * VPITCH + r4;
            const int vb1o = (8 * kc + q + 4) * VPITCH + r4;
            #pragma unroll
            for (int nc = 0; nc < 8; nc++) {
                uint32_t b0 = fu(Vs[vb0o + 8 * nc]);
                uint32_t b1 = fu(Vs[vb1o + 8 * nc]);
                mma8(o[nc], a, b0, b1);
            }
        }
        __syncthreads();   // reads done before next iteration's cp.async
    }

    // epilogue
    l0 += __shfl_xor_sync(0xffffffffu, l0, 1);
    l0 += __shfl_xor_sync(0xffffffffu, l0, 2);
    l1 += __shfl_xor_sync(0xffffffffu, l1, 1);
    l1 += __shfl_xor_sync(0xffffffffu, l1, 2);
    const float inv0 = 1.0f / l0, inv1 = 1.0f / l1;

    float* ob = out + (b * TDIM + row_lo) * HDIM;
    #pragma unroll
    for (int nc = 0; nc < 8; nc++) {
        const int col = 8 * nc + 2 * q;
        *(float2*)&ob[col]            = make_float2(o[nc].x * inv0, o[nc].y * inv0);
        *(float2*)&ob[8 * HDIM + col] = make_float2(o[nc].z * inv1, o[nc].w * inv1);
    }
}

// ---------------------------------------------------------------------------
extern "C" void kernel_launch(void* const* d_in, const int* in_sizes, int n_in,
                              void* d_out, int out_size)
{
    const float* x  = (const float*)d_in[0];
    const float* Wk = (const float*)d_in[1];
    const float* Wq = (const float*)d_in[2];
    const float* Wv = (const float*)d_in[3];
    float* out = (float*)d_out;

    proj_kernel<<<BT / 128, 256>>>(x, Wk, Wq, Wv);

    cudaFuncSetAttribute(attn_kernel,
                         cudaFuncAttributeMaxDynamicSharedMemorySize, ASMEM);
    dim3 agrid(NQT, BATCH);
    attn_kernel<<<agrid, 128, ASMEM>>>(out);
}